// round 16
// baseline (speedup 1.0000x reference)
#include <cuda_runtime.h>
#include <cuda_bf16.h>
#include <math.h>
#include <cstdint>

#define Nn   50000
#define Ee   600000
#define FA   78
#define Dd   128
#define Hh   8
#define EDd  12
#define Ll   4
#define Bb   512
#define DFFd 512
#define MP   50048

typedef unsigned short ushort_t;

// ---- pre-split weight buffer layout (elements) ----
#define OFF_EMB 0
#define SZ_EMB  (128 * 128)
#define OFF_QKV (OFF_EMB + SZ_EMB)
#define SZ_QKV  (512 * 128)
#define OFF_FF1 (OFF_QKV + 4 * SZ_QKV)
#define OFF_FF2 (OFF_FF1 + 4 * SZ_QKV)
#define OFF_OUT (OFF_FF2 + 4 * SZ_QKV)
#define W_TOTAL (OFF_OUT + SZ_EMB)

// ---------------- scratch (device globals) ----------------
__device__ float    g_h[(size_t)Nn * Dd];
__device__ float    g_qkvs[(size_t)Nn * 4 * Dd];
__device__ float    g_packb[4 * 4 * Dd];
__device__ float    g_pool[Bb * Dd];
__device__ float    g_cnt[Bb];
__device__ ushort_t g_Wh[W_TOTAL];
__device__ ushort_t g_Wl[W_TOTAL];
__device__ ushort_t g_Ath[(size_t)MP * Dd];
__device__ ushort_t g_Atl[(size_t)MP * Dd];
__device__ ushort_t g_Fth[(size_t)MP * DFFd];
__device__ ushort_t g_Ftl[(size_t)MP * DFFd];
__device__ int      g_rowptr[Nn + 1];
__device__ int      g_pos[Nn];
__device__ int      g_eidx[Ee];

// ---------------- helpers ----------------
__device__ __forceinline__ uint32_t smem_u32(const void* p) {
    uint32_t a;
    asm("{ .reg .u64 t; cvta.to.shared.u64 t, %1; cvt.u32.u64 %0, t; }" : "=r"(a) : "l"(p));
    return a;
}
__device__ __forceinline__ void cp16(uint32_t dst, const void* src) {
    asm volatile("cp.async.cg.shared.global [%0], [%1], 16;" :: "r"(dst), "l"(src));
}
__device__ __forceinline__ void cp_commit() { asm volatile("cp.async.commit_group;" ::: "memory"); }
template <int N> __device__ __forceinline__ void cp_wait() {
    asm volatile("cp.async.wait_group %0;" :: "n"(N) : "memory");
}
__device__ __forceinline__ void ldsm4(uint32_t& r0, uint32_t& r1, uint32_t& r2, uint32_t& r3, uint32_t addr) {
    asm volatile("ldmatrix.sync.aligned.m8n8.x4.shared.b16 {%0,%1,%2,%3}, [%4];"
                 : "=r"(r0), "=r"(r1), "=r"(r2), "=r"(r3) : "r"(addr));
}
__device__ __forceinline__ void mma_bf16(float& c0, float& c1, float& c2, float& c3,
                                         uint32_t a0, uint32_t a1, uint32_t a2, uint32_t a3,
                                         uint32_t b0, uint32_t b1) {
    asm volatile(
        "mma.sync.aligned.m16n8k16.row.col.f32.bf16.bf16.f32 "
        "{%0,%1,%2,%3}, {%4,%5,%6,%7}, {%8,%9}, {%0,%1,%2,%3};"
        : "+f"(c0), "+f"(c1), "+f"(c2), "+f"(c3)
        : "r"(a0), "r"(a1), "r"(a2), "r"(a3), "r"(b0), "r"(b1));
}
__device__ __forceinline__ void split2(float x, float y, uint32_t& hp, uint32_t& lp) {
    __nv_bfloat16 hx = __float2bfloat16(x), hy = __float2bfloat16(y);
    __nv_bfloat16 lx = __float2bfloat16(x - __bfloat162float(hx));
    __nv_bfloat16 ly = __float2bfloat16(y - __bfloat162float(hy));
    hp = (uint32_t)__bfloat16_as_ushort(hx) | ((uint32_t)__bfloat16_as_ushort(hy) << 16);
    lp = (uint32_t)__bfloat16_as_ushort(lx) | ((uint32_t)__bfloat16_as_ushort(ly) << 16);
}

// ---------------- one-shot: split ALL weights + pack biases + zero rowptr --------
__global__ void prep_all_k(
    const float* __restrict__ Wemb, const float* __restrict__ Wq,
    const float* __restrict__ Wk, const float* __restrict__ Wv,
    const float* __restrict__ Ws, const float* __restrict__ Wf1,
    const float* __restrict__ Wf2, const float* __restrict__ Wout,
    const float* __restrict__ bq, const float* __restrict__ bk,
    const float* __restrict__ bv, const float* __restrict__ bs)
{
    int i = blockIdx.x * 256 + threadIdx.x;
    if (i < Nn + 1) g_rowptr[i] = 0;
    if (i < 4 * 4 * Dd) {
        int l = i >> 9, c = i & 511, s = c >> 7, j = c & 127;
        const float* bb = (s == 0) ? bq : (s == 1) ? bk : (s == 2) ? bv : bs;
        g_packb[i] = bb[l * Dd + j];
    }
    if (i >= W_TOTAL) return;
    float v;
    if (i < OFF_QKV) {
        int n = i >> 7, k = i & 127;
        v = (k < FA) ? Wemb[k * Dd + n] : 0.f;
    } else if (i < OFF_FF1) {
        int t = i - OFF_QKV, l = t >> 16, r = t & 65535;
        int n = r >> 7, k = r & 127, sub = n >> 7, nn = n & 127;
        const float* W = (sub == 0) ? Wq : (sub == 1) ? Wk : (sub == 2) ? Wv : Ws;
        v = W[(size_t)l * Dd * Dd + k * Dd + nn];
    } else if (i < OFF_FF2) {
        int t = i - OFF_FF1, l = t >> 16, r = t & 65535;
        int n = r >> 7, k = r & 127;
        v = Wf1[(size_t)l * Dd * DFFd + k * DFFd + n];
    } else if (i < OFF_OUT) {
        int t = i - OFF_FF2, l = t >> 16, r = t & 65535;
        int n = r >> 9, k = r & 511;
        v = Wf2[(size_t)l * DFFd * Dd + k * Dd + n];
    } else {
        int t = i - OFF_OUT;
        int n = t >> 7, k = t & 127;
        v = Wout[k * Dd + n];
    }
    __nv_bfloat16 h = __float2bfloat16(v);
    __nv_bfloat16 lo = __float2bfloat16(v - __bfloat162float(h));
    g_Wh[i] = __bfloat16_as_ushort(h);
    g_Wl[i] = __bfloat16_as_ushort(lo);
}

__global__ void split_a_k(const float* __restrict__ src, int ksrc, int M) {
    int i = blockIdx.x * 256 + threadIdx.x;
    if (i >= M * Dd) return;
    int r = i >> 7, k = i & 127;
    float v = (k < ksrc) ? src[(size_t)r * ksrc + k] : 0.f;
    __nv_bfloat16 h = __float2bfloat16(v);
    __nv_bfloat16 lo = __float2bfloat16(v - __bfloat162float(h));
    g_Ath[(size_t)r * Dd + k] = __bfloat16_as_ushort(h);
    g_Atl[(size_t)r * Dd + k] = __bfloat16_as_ushort(lo);
}

// ---------------- CSR build ----------------
__global__ void csr_hist_k(const int* __restrict__ ei) {
    int i = blockIdx.x * 256 + threadIdx.x;
    int st = gridDim.x * 256;
    for (int e = i; e < Ee; e += st) atomicAdd(&g_rowptr[ei[Ee + e] + 1], 1);
}
__global__ void __launch_bounds__(1024) csr_scan_k() {
    __shared__ int temp[1024];
    __shared__ int carry_s;
    int tid = threadIdx.x;
    if (tid == 0) carry_s = 0;
    __syncthreads();
    for (int base = 0; base < Nn + 1; base += 1024) {
        int i = base + tid;
        int v = (i < Nn + 1) ? g_rowptr[i] : 0;
        temp[tid] = v;
        __syncthreads();
#pragma unroll
        for (int off = 1; off < 1024; off <<= 1) {
            int t = (tid >= off) ? temp[tid - off] : 0;
            __syncthreads();
            temp[tid] += t;
            __syncthreads();
        }
        int incl = temp[tid] + carry_s;
        if (i < Nn + 1) g_rowptr[i] = incl;
        if (i < Nn) g_pos[i] = incl;
        __syncthreads();
        if (tid == 1023) carry_s += temp[1023];
        __syncthreads();
    }
}
__global__ void csr_scatter_k(const int* __restrict__ ei) {
    int i = blockIdx.x * 256 + threadIdx.x;
    int st = gridDim.x * 256;
    for (int e = i; e < Ee; e += st) {
        int p = atomicAdd(&g_pos[ei[Ee + e]], 1);
        g_eidx[p] = e;
    }
}

// ---------------- deep-pipelined split-bf16 HMMA GEMM --------------------------
// k-chunk 16, 4 smem stages, one sync per chunk, 2 CTAs/SM.
// MB = CTA M-tile / 64 (2 -> 128 rows, 1 -> 64 rows; MB=1 halves wave quantization
// for skinny grids like FF2).
// OUT: 0 fp32 C; 1 split bf16; 2 fp32 C + split->Ath/Atl; 3 fused LN2 epilogue.
#define T_STRIDE 24
#define BUF_B    (128 * T_STRIDE * 2)
#define STAGE_B  (4 * BUF_B)
#define NSTAGE   4
#define SMEM_G2  (NSTAGE * STAGE_B)

template <int OUT, int MB>
__global__ void __launch_bounds__(256, 2) gemm2_k(
    const ushort_t* __restrict__ Ah, const ushort_t* __restrict__ Al, int ksa,
    int M, int nc,
    const ushort_t* __restrict__ Bh, const ushort_t* __restrict__ Bl, int ksb,
    const float* __restrict__ bias,
    float* __restrict__ C, ushort_t* __restrict__ Ch, ushort_t* __restrict__ Cl,
    int Nfull, int relu,
    const float* __restrict__ g2p, const float* __restrict__ b2p)
{
    extern __shared__ __align__(16) char smem[];
    const uint32_t sb = smem_u32(smem);

    const int tid  = threadIdx.x;
    const int warp = tid >> 5, lane = tid & 31;
    const int wm = warp & 3, wn = warp >> 2;
    const int bm = blockIdx.x * (MB * 64);
    const int bn = blockIdx.y << 7;

    const int lrow = tid >> 1;            // 0..127
    const int half = tid & 1;

    float acc[MB][8][4];
#pragma unroll
    for (int i = 0; i < MB; i++)
#pragma unroll
        for (int j = 0; j < 8; j++)
#pragma unroll
            for (int q = 0; q < 4; q++) acc[i][j][q] = 0.f;

    auto issue = [&](int c) {
        const int k0 = c << 4;
        const uint32_t st = sb + (c & (NSTAGE - 1)) * STAGE_B;
        const uint32_t drow = lrow * (T_STRIDE * 2) + half * 16;
        if (MB == 2 || lrow < 64) {
            cp16(st + drow,             Ah + (size_t)(bm + lrow) * ksa + k0 + half * 8);
            cp16(st + BUF_B + drow,     Al + (size_t)(bm + lrow) * ksa + k0 + half * 8);
        }
        cp16(st + 2 * BUF_B + drow, Bh + (size_t)(bn + lrow) * ksb + k0 + half * 8);
        cp16(st + 3 * BUF_B + drow, Bl + (size_t)(bn + lrow) * ksb + k0 + half * 8);
        cp_commit();
    };

    issue(0);
    if (nc > 1) issue(1);
    if (nc > 2) issue(2);

    const int a_r = ((lane >> 3) & 1) * 8 + (lane & 7);
    const int a_c = (lane >> 4) * 8;
    const int b_r = (lane >> 4) * 8 + (lane & 7);
    const int b_c = ((lane >> 3) & 1) * 8;

    for (int c = 0; c < nc; c++) {
        if (c + 3 <= nc - 1) cp_wait<2>();
        else if (c + 2 <= nc - 1) cp_wait<1>();
        else cp_wait<0>();
        __syncthreads();
        const uint32_t st = sb + (c & (NSTAGE - 1)) * STAGE_B;
        const uint32_t sAh = st, sAl = st + BUF_B, sBh = st + 2 * BUF_B, sBl = st + 3 * BUF_B;

        uint32_t ah[MB][4], al[MB][4];
#pragma unroll
        for (int mb = 0; mb < MB; mb++) {
            uint32_t off = (uint32_t)((wm * (16 * MB) + mb * 16 + a_r) * T_STRIDE + a_c) * 2;
            ldsm4(ah[mb][0], ah[mb][1], ah[mb][2], ah[mb][3], sAh + off);
            ldsm4(al[mb][0], al[mb][1], al[mb][2], al[mb][3], sAl + off);
        }
#pragma unroll
        for (int g = 0; g < 2; g++) {
            uint32_t bh[4][2], bl[4][2];
#pragma unroll
            for (int nbp = 0; nbp < 2; nbp++) {
                uint32_t off = (uint32_t)((wn * 64 + g * 32 + nbp * 16 + b_r) * T_STRIDE + b_c) * 2;
                ldsm4(bh[2 * nbp][0], bh[2 * nbp][1], bh[2 * nbp + 1][0], bh[2 * nbp + 1][1], sBh + off);
                ldsm4(bl[2 * nbp][0], bl[2 * nbp][1], bl[2 * nbp + 1][0], bl[2 * nbp + 1][1], sBl + off);
            }
#pragma unroll
            for (int mb = 0; mb < MB; mb++)
#pragma unroll
                for (int nb = 0; nb < 4; nb++) {
                    float* a4 = acc[mb][g * 4 + nb];
                    mma_bf16(a4[0], a4[1], a4[2], a4[3],
                             ah[mb][0], ah[mb][1], ah[mb][2], ah[mb][3], bh[nb][0], bh[nb][1]);
                    mma_bf16(a4[0], a4[1], a4[2], a4[3],
                             ah[mb][0], ah[mb][1], ah[mb][2], ah[mb][3], bl[nb][0], bl[nb][1]);
                    mma_bf16(a4[0], a4[1], a4[2], a4[3],
                             al[mb][0], al[mb][1], al[mb][2], al[mb][3], bh[nb][0], bh[nb][1]);
                }
        }
        if (c + 3 < nc) issue(c + 3);
    }
    __syncthreads();

    const int qr = lane >> 2;
    const int qc = (lane & 3) * 2;

    if (OUT == 3) {
        float* psum = (float*)smem;        // [2][MB*64]
        float* psq  = psum + 2 * MB * 64;
#pragma unroll
        for (int mb = 0; mb < MB; mb++)
#pragma unroll
            for (int hf = 0; hf < 2; hf++) {
                int rl = wm * (16 * MB) + mb * 16 + hf * 8 + qr;
                int r = bm + rl;
                float s_m = 0.f, s_q = 0.f;
#pragma unroll
                for (int nb = 0; nb < 8; nb++) {
                    int cn = wn * 64 + nb * 8 + qc;
                    float h0 = 0.f, h1 = 0.f;
                    if (r < M) {
                        float2 hh = *(const float2*)&g_h[(size_t)r * Dd + cn];
                        h0 = hh.x; h1 = hh.y;
                    }
                    float t0 = acc[mb][nb][hf * 2 + 0] + bias[cn] + h0;
                    float t1 = acc[mb][nb][hf * 2 + 1] + bias[cn + 1] + h1;
                    acc[mb][nb][hf * 2 + 0] = t0;
                    acc[mb][nb][hf * 2 + 1] = t1;
                    s_m += t0 + t1;
                    s_q += t0 * t0 + t1 * t1;
                }
                s_m += __shfl_xor_sync(0xffffffffu, s_m, 1);
                s_q += __shfl_xor_sync(0xffffffffu, s_q, 1);
                s_m += __shfl_xor_sync(0xffffffffu, s_m, 2);
                s_q += __shfl_xor_sync(0xffffffffu, s_q, 2);
                if ((lane & 3) == 0) {
                    psum[wn * (MB * 64) + rl] = s_m;
                    psq [wn * (MB * 64) + rl] = s_q;
                }
            }
        __syncthreads();
#pragma unroll
        for (int mb = 0; mb < MB; mb++)
#pragma unroll
            for (int hf = 0; hf < 2; hf++) {
                int rl = wm * (16 * MB) + mb * 16 + hf * 8 + qr;
                int r = bm + rl;
                if (r >= M) continue;
                float smv = psum[rl] + psum[MB * 64 + rl];
                float sqv = psq[rl]  + psq[MB * 64 + rl];
                float mu = smv * (1.f / 128.f);
                float var = sqv * (1.f / 128.f) - mu * mu;
                float rsv = rsqrtf(var + 1e-5f);
#pragma unroll
                for (int nb = 0; nb < 8; nb++) {
                    int cn = wn * 64 + nb * 8 + qc;
                    float o0 = (acc[mb][nb][hf * 2 + 0] - mu) * rsv * g2p[cn]     + b2p[cn];
                    float o1 = (acc[mb][nb][hf * 2 + 1] - mu) * rsv * g2p[cn + 1] + b2p[cn + 1];
                    *(float2*)&g_h[(size_t)r * Dd + cn] = make_float2(o0, o1);
                    uint32_t hp, lp; split2(o0, o1, hp, lp);
                    *(uint32_t*)&g_Ath[(size_t)r * Dd + cn] = hp;
                    *(uint32_t*)&g_Atl[(size_t)r * Dd + cn] = lp;
                }
            }
        return;
    }

#pragma unroll
    for (int mb = 0; mb < MB; mb++) {
        int r0 = bm + wm * (16 * MB) + mb * 16 + qr;
#pragma unroll
        for (int hf = 0; hf < 2; hf++) {
            int r = r0 + hf * 8;
            if (r >= M) continue;
#pragma unroll
            for (int nb = 0; nb < 8; nb++) {
                int cn = bn + wn * 64 + nb * 8 + qc;
                float v0 = acc[mb][nb][hf * 2 + 0] + bias[cn];
                float v1 = acc[mb][nb][hf * 2 + 1] + bias[cn + 1];
                if (relu) { v0 = fmaxf(v0, 0.f); v1 = fmaxf(v1, 0.f); }
                if (OUT == 0 || OUT == 2)
                    *(float2*)&C[(size_t)r * Nfull + cn] = make_float2(v0, v1);
                if (OUT == 1) {
                    uint32_t hp, lp; split2(v0, v1, hp, lp);
                    *(uint32_t*)&Ch[(size_t)r * Nfull + cn] = hp;
                    *(uint32_t*)&Cl[(size_t)r * Nfull + cn] = lp;
                }
                if (OUT == 2) {
                    uint32_t hp, lp; split2(v0, v1, hp, lp);
                    *(uint32_t*)&g_Ath[(size_t)r * Dd + cn] = hp;
                    *(uint32_t*)&g_Atl[(size_t)r * Dd + cn] = lp;
                }
            }
        }
    }
}

// ---------------- fused gather (R13): pipelined ILP x2, 1 warp per node ----------
__global__ void __launch_bounds__(256) edge_gather_k(
    const int* __restrict__ ei, const float* __restrict__ ea,
    const float* __restrict__ We, const float* __restrict__ be,
    const float* __restrict__ wb, const float* __restrict__ g1v,
    const float* __restrict__ b1v)
{
    __shared__ float sWe[EDd * Dd];
    __shared__ float sbe[Dd], sg1[Dd], sb1[Dd];
    __shared__ float swb[3 * Dd];
    for (int i = threadIdx.x; i < EDd * Dd; i += 256) sWe[i] = We[i];
    for (int i = threadIdx.x; i < Dd; i += 256) { sbe[i] = be[i]; sg1[i] = g1v[i]; sb1[i] = b1v[i]; }
    for (int i = threadIdx.x; i < 3 * Dd; i += 256) swb[i] = wb[i];
    __syncthreads();

    const int warp = threadIdx.x >> 5, lane = threadIdx.x & 31;
    const int n = blockIdx.x * 8 + warp;
    if (n >= Nn) return;
    const int ch = lane * 4;

    const float4 q = *(const float4*)&g_qkvs[(size_t)n * 512 + ch];
    const int s = g_rowptr[n], e = g_rowptr[n + 1];

    float ax = 0.f, ay = 0.f, az = 0.f, aw = 0.f, den = 0.f;
    float bx = 0.f, by = 0.f, bz = 0.f, bw = 0.f, den2 = 0.f;

    int s1c = 0, s2c = 0;
    float ev1c = 0.f, ev2c = 0.f;
    if (s + 1 < e) {
        int e1 = g_eidx[s], e2 = g_eidx[s + 1];
        s1c = ei[e1]; s2c = ei[e2];
        ev1c = (lane < EDd) ? ea[(size_t)e1 * EDd + lane] : 0.f;
        ev2c = (lane < EDd) ? ea[(size_t)e2 * EDd + lane] : 0.f;
    }

    int j = s;
    for (; j + 1 < e; j += 2) {
        int s1n = 0, s2n = 0;
        float ev1n = 0.f, ev2n = 0.f;
        if (j + 3 < e) {
            int e1 = g_eidx[j + 2], e2 = g_eidx[j + 3];
            s1n = ei[e1]; s2n = ei[e2];
            ev1n = (lane < EDd) ? ea[(size_t)e1 * EDd + lane] : 0.f;
            ev2n = (lane < EDd) ? ea[(size_t)e2 * EDd + lane] : 0.f;
        }
        float4 k1 = *(const float4*)&g_qkvs[(size_t)s1c * 512 + 128 + ch];
        float4 k2 = *(const float4*)&g_qkvs[(size_t)s2c * 512 + 128 + ch];
        float4 v1 = *(const float4*)&g_qkvs[(size_t)s1c * 512 + 256 + ch];
        float4 v2 = *(const float4*)&g_qkvs[(size_t)s2c * 512 + 256 + ch];

        float p0 = sbe[ch], p1 = sbe[ch + 1], p2 = sbe[ch + 2], p3 = sbe[ch + 3];
        float r0 = p0, r1 = p1, r2 = p2, r3 = p3;
#pragma unroll
        for (int t = 0; t < EDd; t++) {
            float a1 = __shfl_sync(0xffffffffu, ev1c, t);
            float a2 = __shfl_sync(0xffffffffu, ev2c, t);
            float w0 = sWe[t * Dd + ch], w1 = sWe[t * Dd + ch + 1];
            float w2 = sWe[t * Dd + ch + 2], w3 = sWe[t * Dd + ch + 3];
            p0 += a1 * w0; p1 += a1 * w1; p2 += a1 * w2; p3 += a1 * w3;
            r0 += a2 * w0; r1 += a2 * w1; r2 += a2 * w2; r3 += a2 * w3;
        }
        float d1 = q.x * (k1.x + p0) + q.y * (k1.y + p1) + q.z * (k1.z + p2) + q.w * (k1.w + p3);
        float d2 = q.x * (k2.x + r0) + q.y * (k2.y + r1) + q.z * (k2.z + r2) + q.w * (k2.w + r3);
        d1 += __shfl_xor_sync(0xffffffffu, d1, 1);
        d2 += __shfl_xor_sync(0xffffffffu, d2, 1);
        d1 += __shfl_xor_sync(0xffffffffu, d1, 2);
        d2 += __shfl_xor_sync(0xffffffffu, d2, 2);
        float x1 = __expf(d1 * 0.25f);
        float x2 = __expf(d2 * 0.25f);
        den += x1; den2 += x2;
        ax += (v1.x + p0) * x1; ay += (v1.y + p1) * x1;
        az += (v1.z + p2) * x1; aw += (v1.w + p3) * x1;
        bx += (v2.x + r0) * x2; by += (v2.y + r1) * x2;
        bz += (v2.z + r2) * x2; bw += (v2.w + r3) * x2;

        s1c = s1n; s2c = s2n; ev1c = ev1n; ev2c = ev2n;
    }
    if (j < e) {
        const int e1 = g_eidx[j];
        const int s1 = ei[e1];
        float ev1 = (lane < EDd) ? ea[(size_t)e1 * EDd + lane] : 0.f;
        float4 k1 = *(const float4*)&g_qkvs[(size_t)s1 * 512 + 128 + ch];
        float4 v1 = *(const float4*)&g_qkvs[(size_t)s1 * 512 + 256 + ch];
        float p0 = sbe[ch], p1 = sbe[ch + 1], p2 = sbe[ch + 2], p3 = sbe[ch + 3];
#pragma unroll
        for (int t = 0; t < EDd; t++) {
            float a1 = __shfl_sync(0xffffffffu, ev1, t);
            p0 += a1 * sWe[t * Dd + ch];
            p1 += a1 * sWe[t * Dd + ch + 1];
            p2 += a1 * sWe[t * Dd + ch + 2];
            p3 += a1 * sWe[t * Dd + ch + 3];
        }
        float d1 = q.x * (k1.x + p0) + q.y * (k1.y + p1) + q.z * (k1.z + p2) + q.w * (k1.w + p3);
        d1 += __shfl_xor_sync(0xffffffffu, d1, 1);
        d1 += __shfl_xor_sync(0xffffffffu, d1, 2);
        float x1 = __expf(d1 * 0.25f);
        den += x1;
        ax += (v1.x + p0) * x1; ay += (v1.y + p1) * x1;
        az += (v1.z + p2) * x1; aw += (v1.w + p3) * x1;
    }
    ax += bx; ay += by; az += bz; aw += bw; den += den2;

    float inv = 1.f / (den + 1e-16f);
    ax *= inv; ay *= inv; az *= inv; aw *= inv;

    float4 xr = *(const float4*)&g_qkvs[(size_t)n * 512 + 384 + ch];
    float sdot =
        ax * swb[ch] + ay * swb[ch + 1] + az * swb[ch + 2] + aw * swb[ch + 3] +
        xr.x * swb[128 + ch] + xr.y * swb[128 + ch + 1] + xr.z * swb[128 + ch + 2] + xr.w * swb[128 + ch + 3] +
        (ax - xr.x) * swb[256 + ch] + (ay - xr.y) * swb[256 + ch + 1] +
        (az - xr.z) * swb[256 + ch + 2] + (aw - xr.w) * swb[256 + ch + 3];
#pragma unroll
    for (int o = 16; o; o >>= 1) sdot += __shfl_xor_sync(0xffffffffu, sdot, o);
    float beta = 1.f / (1.f + expf(-sdot));
    float4 hp = *(const float4*)&g_h[(size_t)n * Dd + ch];
    float t0 = beta * xr.x + (1.f - beta) * ax + hp.x;
    float t1 = beta * xr.y + (1.f - beta) * ay + hp.y;
    float t2 = beta * xr.z + (1.f - beta) * az + hp.z;
    float t3 = beta * xr.w + (1.f - beta) * aw + hp.w;
    float sm = t0 + t1 + t2 + t3;
    float sq = t0 * t0 + t1 * t1 + t2 * t2 + t3 * t3;
#pragma unroll
    for (int o = 16; o; o >>= 1) {
        sm += __shfl_xor_sync(0xffffffffu, sm, o);
        sq += __shfl_xor_sync(0xffffffffu, sq, o);
    }
    float mu = sm * (1.f / 128.f);
    float var = sq * (1.f / 128.f) - mu * mu;
    float rs = rsqrtf(var + 1e-5f);
    float4 o4;
    o4.x = (t0 - mu) * rs * sg1[ch]     + sb1[ch];
    o4.y = (t1 - mu) * rs * sg1[ch + 1] + sb1[ch + 1];
    o4.z = (t2 - mu) * rs * sg1[ch + 2] + sb1[ch + 2];
    o4.w = (t3 - mu) * rs * sg1[ch + 3] + sb1[ch + 3];
    *(float4*)&g_h[(size_t)n * Dd + ch] = o4;
    uint32_t h0, l0, h1, l1;
    split2(o4.x, o4.y, h0, l0);
    split2(o4.z, o4.w, h1, l1);
    *(uint2*)&g_Ath[(size_t)n * Dd + ch] = make_uint2(h0, h1);
    *(uint2*)&g_Atl[(size_t)n * Dd + ch] = make_uint2(l0, l1);
}

// ---------------- pooling ----------------
__global__ void zero_pool_k() {
    int i = blockIdx.x * blockDim.x + threadIdx.x;
    int st = gridDim.x * blockDim.x;
    for (int j = i; j < Bb * Dd; j += st) g_pool[j] = 0.f;
    for (int j = i; j < Bb; j += st) g_cnt[j] = 0.f;
}
__global__ void __launch_bounds__(256) pool_k(const int* __restrict__ batch) {
    int warp = threadIdx.x >> 5, lane = threadIdx.x & 31;
    int n = blockIdx.x * 8 + warp;
    if (n >= Nn) return;
    int b = batch[n];
    int ch = lane * 4;
    float4 h4 = *(const float4*)&g_h[(size_t)n * Dd + ch];
    float* dp = &g_pool[(size_t)b * Dd + ch];
    asm volatile("red.global.add.v4.f32 [%0], {%1,%2,%3,%4};"
                 :: "l"(dp), "f"(h4.x), "f"(h4.y), "f"(h4.z), "f"(h4.w) : "memory");
    if (lane == 0) atomicAdd(&g_cnt[b], 1.f);
}
__global__ void __launch_bounds__(256) pool_div_k() {
    int warp = threadIdx.x >> 5, lane = threadIdx.x & 31;
    int b = blockIdx.x * 8 + warp;
    if (b >= Bb) return;
    float c = fmaxf(g_cnt[b], 1.f);
    int ch = lane * 4;
    float4 p = *(const float4*)&g_pool[(size_t)b * Dd + ch];
    p.x /= c; p.y /= c; p.z /= c; p.w /= c;
    *(float4*)&g_pool[(size_t)b * Dd + ch] = p;
}

// ---------------- host ----------------
extern "C" void kernel_launch(void* const* d_in, const int* in_sizes, int n_in,
                              void* d_out, int out_size)
{
    (void)in_sizes; (void)n_in; (void)out_size;
    const float* x     = (const float*)d_in[0];
    const float* ea    = (const float*)d_in[1];
    const int*   ei    = (const int*)  d_in[2];
    const int*   batch = (const int*)  d_in[3];
    const float* Wemb  = (const float*)d_in[4];
    const float* bemb  = (const float*)d_in[5];
    const float* Wout  = (const float*)d_in[6];
    const float* bout  = (const float*)d_in[7];
    const float* Wq = (const float*)d_in[8];  const float* bq = (const float*)d_in[9];
    const float* Wk = (const float*)d_in[10]; const float* bk = (const float*)d_in[11];
    const float* Wv = (const float*)d_in[12]; const float* bv = (const float*)d_in[13];
    const float* We = (const float*)d_in[14]; const float* be = (const float*)d_in[15];
    const float* Ws = (const float*)d_in[16]; const float* bs = (const float*)d_in[17];
    const float* Wbeta = (const float*)d_in[18];
    const float* g1 = (const float*)d_in[19]; const float* b1 = (const float*)d_in[20];
    const float* g2 = (const float*)d_in[21]; const float* b2 = (const float*)d_in[22];
    const float* Wf1 = (const float*)d_in[23]; const float* bf1 = (const float*)d_in[24];
    const float* Wf2 = (const float*)d_in[25]; const float* bf2 = (const float*)d_in[26];
    float* out = (float*)d_out;

    float *p_h, *p_qkvs, *p_packb, *p_pool;
    ushort_t *p_Wh, *p_Wl, *p_Ath, *p_Atl, *p_Fth, *p_Ftl;
    cudaGetSymbolAddress((void**)&p_h,     g_h);
    cudaGetSymbolAddress((void**)&p_qkvs,  g_qkvs);
    cudaGetSymbolAddress((void**)&p_packb, g_packb);
    cudaGetSymbolAddress((void**)&p_pool,  g_pool);
    cudaGetSymbolAddress((void**)&p_Wh,    g_Wh);
    cudaGetSymbolAddress((void**)&p_Wl,    g_Wl);
    cudaGetSymbolAddress((void**)&p_Ath,   g_Ath);
    cudaGetSymbolAddress((void**)&p_Atl,   g_Atl);
    cudaGetSymbolAddress((void**)&p_Fth,   g_Fth);
    cudaGetSymbolAddress((void**)&p_Ftl,   g_Ftl);

    cudaFuncSetAttribute((const void*)gemm2_k<0, 2>, cudaFuncAttributeMaxDynamicSharedMemorySize, SMEM_G2);
    cudaFuncSetAttribute((const void*)gemm2_k<1, 2>, cudaFuncAttributeMaxDynamicSharedMemorySize, SMEM_G2);
    cudaFuncSetAttribute((const void*)gemm2_k<2, 1>, cudaFuncAttributeMaxDynamicSharedMemorySize, SMEM_G2);
    cudaFuncSetAttribute((const void*)gemm2_k<3, 1>, cudaFuncAttributeMaxDynamicSharedMemorySize, SMEM_G2);

    dim3 blk(256);
    const int mt  = (Nn + 127) / 128;     // 391 (MB=2 grids)
    const int mt1 = (Nn + 63) / 64;       // 782 (MB=1 grids)
    const int ng  = (Nn + 7) / 8;

    split_a_k<<<(Nn * Dd + 255) / 256, blk>>>(x, FA, Nn);
    prep_all_k<<<(W_TOTAL + 255) / 256, blk>>>(Wemb, Wq, Wk, Wv, Ws, Wf1, Wf2, Wout,
                                               bq, bk, bv, bs);
    gemm2_k<2, 1><<<dim3(mt1, 1), blk, SMEM_G2>>>(p_Ath, p_Atl, Dd, Nn, 8,
                                                  p_Wh + OFF_EMB, p_Wl + OFF_EMB, Dd,
                                                  bemb, p_h, nullptr, nullptr, Dd, 0, nullptr, nullptr);
    gemm2_k<0, 2><<<dim3(mt, 4), blk, SMEM_G2>>>(p_Ath, p_Atl, Dd, Nn, 8,
                                                 p_Wh + OFF_QKV, p_Wl + OFF_QKV, Dd,
                                                 p_packb, p_qkvs, nullptr, nullptr, 4 * Dd, 0, nullptr, nullptr);
    csr_hist_k<<<1024, blk>>>(ei);
    csr_scan_k<<<1, 1024>>>();
    csr_scatter_k<<<1024, blk>>>(ei);

    for (int l = 0; l < Ll; l++) {
        if (l > 0)
            gemm2_k<0, 2><<<dim3(mt, 4), blk, SMEM_G2>>>(p_Ath, p_Atl, Dd, Nn, 8,
                                                         p_Wh + OFF_QKV + l * SZ_QKV, p_Wl + OFF_QKV + l * SZ_QKV, Dd,
                                                         p_packb + l * 4 * Dd, p_qkvs, nullptr, nullptr, 4 * Dd, 0,
                                                         nullptr, nullptr);

        edge_gather_k<<<ng, blk>>>(ei, ea, We + (size_t)l * EDd * Dd, be + l * Dd,
                                   Wbeta + l * 3 * Dd, g1 + l * Dd, b1 + l * Dd);

        gemm2_k<1, 2><<<dim3(mt, 4), blk, SMEM_G2>>>(p_Ath, p_Atl, Dd, Nn, 8,
                                                     p_Wh + OFF_FF1 + l * SZ_QKV, p_Wl + OFF_FF1 + l * SZ_QKV, Dd,
                                                     bf1 + l * DFFd, nullptr, p_Fth, p_Ftl, DFFd, 1, nullptr, nullptr);

        gemm2_k<3, 1><<<dim3(mt1, 1), blk, SMEM_G2>>>(p_Fth, p_Ftl, DFFd, Nn, 32,
                                                      p_Wh + OFF_FF2 + l * SZ_QKV, p_Wl + OFF_FF2 + l * SZ_QKV, DFFd,
                                                      bf2 + l * Dd, nullptr, nullptr, nullptr, Dd, 0,
                                                      g2 + l * Dd, b2 + l * Dd);
    }

    zero_pool_k<<<256, blk>>>();
    pool_k<<<ng, blk>>>(batch);
    pool_div_k<<<(Bb + 7) / 8, blk>>>();
    split_a_k<<<(Bb * Dd + 255) / 256, blk>>>(p_pool, Dd, Bb);
    gemm2_k<0, 2><<<dim3(4, 1), blk, SMEM_G2>>>(p_Ath, p_Atl, Dd, Bb, 8,
                                                p_Wh + OFF_OUT, p_Wl + OFF_OUT, Dd,
                                                bout, out, nullptr, nullptr, Dd, 0, nullptr, nullptr);
}

// round 17
// speedup vs baseline: 1.0466x; 1.0466x over previous
#include <cuda_runtime.h>
#include <cuda_bf16.h>
#include <math.h>
#include <cstdint>

#define Nn   50000
#define Ee   600000
#define FA   78
#define Dd   128
#define Hh   8
#define EDd  12
#define Ll   4
#define Bb   512
#define DFFd 512
#define MP   50048

typedef unsigned short ushort_t;

// ---- pre-split weight buffer layout (elements) ----
#define OFF_EMB 0
#define SZ_EMB  (128 * 128)
#define OFF_QKV (OFF_EMB + SZ_EMB)
#define SZ_QKV  (512 * 128)
#define OFF_FF1 (OFF_QKV + 4 * SZ_QKV)
#define OFF_FF2 (OFF_FF1 + 4 * SZ_QKV)
#define OFF_OUT (OFF_FF2 + 4 * SZ_QKV)
#define W_TOTAL (OFF_OUT + SZ_EMB)

// ---------------- scratch (device globals) ----------------
__device__ float    g_h[(size_t)Nn * Dd];
__device__ float    g_qkvs[(size_t)Nn * 4 * Dd];
__device__ float    g_packb[4 * 4 * Dd];
__device__ float    g_pool[Bb * Dd];
__device__ float    g_cnt[Bb];
__device__ ushort_t g_Wh[W_TOTAL];
__device__ ushort_t g_Wl[W_TOTAL];
__device__ ushort_t g_Ath[(size_t)MP * Dd];
__device__ ushort_t g_Atl[(size_t)MP * Dd];
__device__ ushort_t g_Fth[(size_t)MP * DFFd];
__device__ ushort_t g_Ftl[(size_t)MP * DFFd];
__device__ int      g_rowptr[Nn + 1];
__device__ int      g_pos[Nn];
__device__ int      g_eidx[Ee];

// ---------------- helpers ----------------
__device__ __forceinline__ uint32_t smem_u32(const void* p) {
    uint32_t a;
    asm("{ .reg .u64 t; cvta.to.shared.u64 t, %1; cvt.u32.u64 %0, t; }" : "=r"(a) : "l"(p));
    return a;
}
__device__ __forceinline__ void cp16(uint32_t dst, const void* src) {
    asm volatile("cp.async.cg.shared.global [%0], [%1], 16;" :: "r"(dst), "l"(src));
}
__device__ __forceinline__ void cp_commit() { asm volatile("cp.async.commit_group;" ::: "memory"); }
template <int N> __device__ __forceinline__ void cp_wait() {
    asm volatile("cp.async.wait_group %0;" :: "n"(N) : "memory");
}
__device__ __forceinline__ void ldsm4(uint32_t& r0, uint32_t& r1, uint32_t& r2, uint32_t& r3, uint32_t addr) {
    asm volatile("ldmatrix.sync.aligned.m8n8.x4.shared.b16 {%0,%1,%2,%3}, [%4];"
                 : "=r"(r0), "=r"(r1), "=r"(r2), "=r"(r3) : "r"(addr));
}
__device__ __forceinline__ void mma_bf16(float& c0, float& c1, float& c2, float& c3,
                                         uint32_t a0, uint32_t a1, uint32_t a2, uint32_t a3,
                                         uint32_t b0, uint32_t b1) {
    asm volatile(
        "mma.sync.aligned.m16n8k16.row.col.f32.bf16.bf16.f32 "
        "{%0,%1,%2,%3}, {%4,%5,%6,%7}, {%8,%9}, {%0,%1,%2,%3};"
        : "+f"(c0), "+f"(c1), "+f"(c2), "+f"(c3)
        : "r"(a0), "r"(a1), "r"(a2), "r"(a3), "r"(b0), "r"(b1));
}
__device__ __forceinline__ void split2(float x, float y, uint32_t& hp, uint32_t& lp) {
    __nv_bfloat16 hx = __float2bfloat16(x), hy = __float2bfloat16(y);
    __nv_bfloat16 lx = __float2bfloat16(x - __bfloat162float(hx));
    __nv_bfloat16 ly = __float2bfloat16(y - __bfloat162float(hy));
    hp = (uint32_t)__bfloat16_as_ushort(hx) | ((uint32_t)__bfloat16_as_ushort(hy) << 16);
    lp = (uint32_t)__bfloat16_as_ushort(lx) | ((uint32_t)__bfloat16_as_ushort(ly) << 16);
}

// ---------------- one-shot: split ALL weights + pack biases + zero state ---------
__global__ void prep_all_k(
    const float* __restrict__ Wemb, const float* __restrict__ Wq,
    const float* __restrict__ Wk, const float* __restrict__ Wv,
    const float* __restrict__ Ws, const float* __restrict__ Wf1,
    const float* __restrict__ Wf2, const float* __restrict__ Wout,
    const float* __restrict__ bq, const float* __restrict__ bk,
    const float* __restrict__ bv, const float* __restrict__ bs)
{
    int i = blockIdx.x * 256 + threadIdx.x;
    if (i < Nn + 1) g_rowptr[i] = 0;
    if (i < Bb * Dd) g_pool[i] = 0.f;
    if (i < Bb) g_cnt[i] = 0.f;
    if (i < 4 * 4 * Dd) {
        int l = i >> 9, c = i & 511, s = c >> 7, j = c & 127;
        const float* bb = (s == 0) ? bq : (s == 1) ? bk : (s == 2) ? bv : bs;
        g_packb[i] = bb[l * Dd + j];
    }
    if (i >= W_TOTAL) return;
    float v;
    if (i < OFF_QKV) {
        int n = i >> 7, k = i & 127;
        v = (k < FA) ? Wemb[k * Dd + n] : 0.f;
    } else if (i < OFF_FF1) {
        int t = i - OFF_QKV, l = t >> 16, r = t & 65535;
        int n = r >> 7, k = r & 127, sub = n >> 7, nn = n & 127;
        const float* W = (sub == 0) ? Wq : (sub == 1) ? Wk : (sub == 2) ? Wv : Ws;
        v = W[(size_t)l * Dd * Dd + k * Dd + nn];
    } else if (i < OFF_FF2) {
        int t = i - OFF_FF1, l = t >> 16, r = t & 65535;
        int n = r >> 7, k = r & 127;
        v = Wf1[(size_t)l * Dd * DFFd + k * DFFd + n];
    } else if (i < OFF_OUT) {
        int t = i - OFF_FF2, l = t >> 16, r = t & 65535;
        int n = r >> 9, k = r & 511;
        v = Wf2[(size_t)l * DFFd * Dd + k * Dd + n];
    } else {
        int t = i - OFF_OUT;
        int n = t >> 7, k = t & 127;
        v = Wout[k * Dd + n];
    }
    __nv_bfloat16 h = __float2bfloat16(v);
    __nv_bfloat16 lo = __float2bfloat16(v - __bfloat162float(h));
    g_Wh[i] = __bfloat16_as_ushort(h);
    g_Wl[i] = __bfloat16_as_ushort(lo);
}

__global__ void split_a_k(const float* __restrict__ src, int ksrc, int M) {
    int i = blockIdx.x * 256 + threadIdx.x;
    if (i >= M * Dd) return;
    int r = i >> 7, k = i & 127;
    float v = (k < ksrc) ? src[(size_t)r * ksrc + k] : 0.f;
    __nv_bfloat16 h = __float2bfloat16(v);
    __nv_bfloat16 lo = __float2bfloat16(v - __bfloat162float(h));
    g_Ath[(size_t)r * Dd + k] = __bfloat16_as_ushort(h);
    g_Atl[(size_t)r * Dd + k] = __bfloat16_as_ushort(lo);
}

// ---------------- CSR build ----------------
__global__ void csr_hist_k(const int* __restrict__ ei) {
    int i = blockIdx.x * 256 + threadIdx.x;
    int st = gridDim.x * 256;
    for (int e = i; e < Ee; e += st) atomicAdd(&g_rowptr[ei[Ee + e] + 1], 1);
}
__global__ void __launch_bounds__(1024) csr_scan_k() {
    __shared__ int temp[1024];
    __shared__ int carry_s;
    int tid = threadIdx.x;
    if (tid == 0) carry_s = 0;
    __syncthreads();
    for (int base = 0; base < Nn + 1; base += 1024) {
        int i = base + tid;
        int v = (i < Nn + 1) ? g_rowptr[i] : 0;
        temp[tid] = v;
        __syncthreads();
#pragma unroll
        for (int off = 1; off < 1024; off <<= 1) {
            int t = (tid >= off) ? temp[tid - off] : 0;
            __syncthreads();
            temp[tid] += t;
            __syncthreads();
        }
        int incl = temp[tid] + carry_s;
        if (i < Nn + 1) g_rowptr[i] = incl;
        if (i < Nn) g_pos[i] = incl;
        __syncthreads();
        if (tid == 1023) carry_s += temp[1023];
        __syncthreads();
    }
}
__global__ void csr_scatter_k(const int* __restrict__ ei) {
    int i = blockIdx.x * 256 + threadIdx.x;
    int st = gridDim.x * 256;
    for (int e = i; e < Ee; e += st) {
        int p = atomicAdd(&g_pos[ei[Ee + e]], 1);
        g_eidx[p] = e;
    }
}

// ---------------- deep-pipelined split-bf16 HMMA GEMM (R15 config) --------------
// k-chunk 16, 4 smem stages, one sync per chunk, 2 CTAs/SM.
// OUT: 0 fp32 C; 1 split bf16; 2 fp32 C + split->Ath/Atl; 3 fused LN2 epilogue.
#define T_STRIDE 24
#define BUF_B    (128 * T_STRIDE * 2)
#define STAGE_B  (4 * BUF_B)
#define NSTAGE   4
#define SMEM_G2  (NSTAGE * STAGE_B)

template <int OUT>
__global__ void __launch_bounds__(256, 2) gemm2_k(
    const ushort_t* __restrict__ Ah, const ushort_t* __restrict__ Al, int ksa,
    int M, int nc,
    const ushort_t* __restrict__ Bh, const ushort_t* __restrict__ Bl, int ksb,
    const float* __restrict__ bias,
    float* __restrict__ C, ushort_t* __restrict__ Ch, ushort_t* __restrict__ Cl,
    int Nfull, int relu,
    const float* __restrict__ g2p, const float* __restrict__ b2p)
{
    extern __shared__ __align__(16) char smem[];
    const uint32_t sb = smem_u32(smem);

    const int tid  = threadIdx.x;
    const int warp = tid >> 5, lane = tid & 31;
    const int wm = warp & 3, wn = warp >> 2;
    const int bm = blockIdx.x << 7;
    const int bn = blockIdx.y << 7;

    const int lrow = tid >> 1;
    const int half = tid & 1;

    float acc[2][8][4];
#pragma unroll
    for (int i = 0; i < 2; i++)
#pragma unroll
        for (int j = 0; j < 8; j++)
#pragma unroll
            for (int q = 0; q < 4; q++) acc[i][j][q] = 0.f;

    auto issue = [&](int c) {
        const int k0 = c << 4;
        const uint32_t st = sb + (c & (NSTAGE - 1)) * STAGE_B;
        const uint32_t drow = lrow * (T_STRIDE * 2) + half * 16;
        cp16(st + drow,              Ah + (size_t)(bm + lrow) * ksa + k0 + half * 8);
        cp16(st + BUF_B + drow,      Al + (size_t)(bm + lrow) * ksa + k0 + half * 8);
        cp16(st + 2 * BUF_B + drow,  Bh + (size_t)(bn + lrow) * ksb + k0 + half * 8);
        cp16(st + 3 * BUF_B + drow,  Bl + (size_t)(bn + lrow) * ksb + k0 + half * 8);
        cp_commit();
    };

    issue(0);
    if (nc > 1) issue(1);
    if (nc > 2) issue(2);

    const int a_r = ((lane >> 3) & 1) * 8 + (lane & 7);
    const int a_c = (lane >> 4) * 8;
    const int b_r = (lane >> 4) * 8 + (lane & 7);
    const int b_c = ((lane >> 3) & 1) * 8;

    for (int c = 0; c < nc; c++) {
        if (c + 3 <= nc - 1) cp_wait<2>();
        else if (c + 2 <= nc - 1) cp_wait<1>();
        else cp_wait<0>();
        __syncthreads();
        const uint32_t st = sb + (c & (NSTAGE - 1)) * STAGE_B;
        const uint32_t sAh = st, sAl = st + BUF_B, sBh = st + 2 * BUF_B, sBl = st + 3 * BUF_B;

        uint32_t ah[2][4], al[2][4];
#pragma unroll
        for (int mb = 0; mb < 2; mb++) {
            uint32_t off = (uint32_t)((wm * 32 + mb * 16 + a_r) * T_STRIDE + a_c) * 2;
            ldsm4(ah[mb][0], ah[mb][1], ah[mb][2], ah[mb][3], sAh + off);
            ldsm4(al[mb][0], al[mb][1], al[mb][2], al[mb][3], sAl + off);
        }
#pragma unroll
        for (int g = 0; g < 2; g++) {
            uint32_t bh[4][2], bl[4][2];
#pragma unroll
            for (int nbp = 0; nbp < 2; nbp++) {
                uint32_t off = (uint32_t)((wn * 64 + g * 32 + nbp * 16 + b_r) * T_STRIDE + b_c) * 2;
                ldsm4(bh[2 * nbp][0], bh[2 * nbp][1], bh[2 * nbp + 1][0], bh[2 * nbp + 1][1], sBh + off);
                ldsm4(bl[2 * nbp][0], bl[2 * nbp][1], bl[2 * nbp + 1][0], bl[2 * nbp + 1][1], sBl + off);
            }
#pragma unroll
            for (int mb = 0; mb < 2; mb++)
#pragma unroll
                for (int nb = 0; nb < 4; nb++) {
                    float* a4 = acc[mb][g * 4 + nb];
                    mma_bf16(a4[0], a4[1], a4[2], a4[3],
                             ah[mb][0], ah[mb][1], ah[mb][2], ah[mb][3], bh[nb][0], bh[nb][1]);
                    mma_bf16(a4[0], a4[1], a4[2], a4[3],
                             ah[mb][0], ah[mb][1], ah[mb][2], ah[mb][3], bl[nb][0], bl[nb][1]);
                    mma_bf16(a4[0], a4[1], a4[2], a4[3],
                             al[mb][0], al[mb][1], al[mb][2], al[mb][3], bh[nb][0], bh[nb][1]);
                }
        }
        if (c + 3 < nc) issue(c + 3);
    }
    __syncthreads();

    const int qr = lane >> 2;
    const int qc = (lane & 3) * 2;

    if (OUT == 3) {
        float* psum = (float*)smem;        // [2][128]
        float* psq  = psum + 256;          // [2][128]
#pragma unroll
        for (int mb = 0; mb < 2; mb++)
#pragma unroll
            for (int hf = 0; hf < 2; hf++) {
                int rl = wm * 32 + mb * 16 + hf * 8 + qr;
                int r = bm + rl;
                float s_m = 0.f, s_q = 0.f;
#pragma unroll
                for (int nb = 0; nb < 8; nb++) {
                    int cn = wn * 64 + nb * 8 + qc;
                    float h0 = 0.f, h1 = 0.f;
                    if (r < M) {
                        float2 hh = *(const float2*)&g_h[(size_t)r * Dd + cn];
                        h0 = hh.x; h1 = hh.y;
                    }
                    float t0 = acc[mb][nb][hf * 2 + 0] + bias[cn] + h0;
                    float t1 = acc[mb][nb][hf * 2 + 1] + bias[cn + 1] + h1;
                    acc[mb][nb][hf * 2 + 0] = t0;
                    acc[mb][nb][hf * 2 + 1] = t1;
                    s_m += t0 + t1;
                    s_q += t0 * t0 + t1 * t1;
                }
                s_m += __shfl_xor_sync(0xffffffffu, s_m, 1);
                s_q += __shfl_xor_sync(0xffffffffu, s_q, 1);
                s_m += __shfl_xor_sync(0xffffffffu, s_m, 2);
                s_q += __shfl_xor_sync(0xffffffffu, s_q, 2);
                if ((lane & 3) == 0) {
                    psum[wn * 128 + rl] = s_m;
                    psq [wn * 128 + rl] = s_q;
                }
            }
        __syncthreads();
#pragma unroll
        for (int mb = 0; mb < 2; mb++)
#pragma unroll
            for (int hf = 0; hf < 2; hf++) {
                int rl = wm * 32 + mb * 16 + hf * 8 + qr;
                int r = bm + rl;
                if (r >= M) continue;
                float smv = psum[rl] + psum[128 + rl];
                float sqv = psq[rl]  + psq[128 + rl];
                float mu = smv * (1.f / 128.f);
                float var = sqv * (1.f / 128.f) - mu * mu;
                float rsv = rsqrtf(var + 1e-5f);
#pragma unroll
                for (int nb = 0; nb < 8; nb++) {
                    int cn = wn * 64 + nb * 8 + qc;
                    float o0 = (acc[mb][nb][hf * 2 + 0] - mu) * rsv * g2p[cn]     + b2p[cn];
                    float o1 = (acc[mb][nb][hf * 2 + 1] - mu) * rsv * g2p[cn + 1] + b2p[cn + 1];
                    *(float2*)&g_h[(size_t)r * Dd + cn] = make_float2(o0, o1);
                    uint32_t hp, lp; split2(o0, o1, hp, lp);
                    *(uint32_t*)&g_Ath[(size_t)r * Dd + cn] = hp;
                    *(uint32_t*)&g_Atl[(size_t)r * Dd + cn] = lp;
                }
            }
        return;
    }

#pragma unroll
    for (int mb = 0; mb < 2; mb++) {
        int r0 = bm + wm * 32 + mb * 16 + qr;
#pragma unroll
        for (int hf = 0; hf < 2; hf++) {
            int r = r0 + hf * 8;
            if (r >= M) continue;
#pragma unroll
            for (int nb = 0; nb < 8; nb++) {
                int cn = bn + wn * 64 + nb * 8 + qc;
                float v0 = acc[mb][nb][hf * 2 + 0] + bias[cn];
                float v1 = acc[mb][nb][hf * 2 + 1] + bias[cn + 1];
                if (relu) { v0 = fmaxf(v0, 0.f); v1 = fmaxf(v1, 0.f); }
                if (OUT == 0 || OUT == 2)
                    *(float2*)&C[(size_t)r * Nfull + cn] = make_float2(v0, v1);
                if (OUT == 1) {
                    uint32_t hp, lp; split2(v0, v1, hp, lp);
                    *(uint32_t*)&Ch[(size_t)r * Nfull + cn] = hp;
                    *(uint32_t*)&Cl[(size_t)r * Nfull + cn] = lp;
                }
                if (OUT == 2) {
                    uint32_t hp, lp; split2(v0, v1, hp, lp);
                    *(uint32_t*)&g_Ath[(size_t)r * Dd + cn] = hp;
                    *(uint32_t*)&g_Atl[(size_t)r * Dd + cn] = lp;
                }
            }
        }
    }
}

// ---------------- fused gather (R13): pipelined ILP x2, 1 warp per node ----------
__global__ void __launch_bounds__(256) edge_gather_k(
    const int* __restrict__ ei, const float* __restrict__ ea,
    const float* __restrict__ We, const float* __restrict__ be,
    const float* __restrict__ wb, const float* __restrict__ g1v,
    const float* __restrict__ b1v)
{
    __shared__ float sWe[EDd * Dd];
    __shared__ float sbe[Dd], sg1[Dd], sb1[Dd];
    __shared__ float swb[3 * Dd];
    for (int i = threadIdx.x; i < EDd * Dd; i += 256) sWe[i] = We[i];
    for (int i = threadIdx.x; i < Dd; i += 256) { sbe[i] = be[i]; sg1[i] = g1v[i]; sb1[i] = b1v[i]; }
    for (int i = threadIdx.x; i < 3 * Dd; i += 256) swb[i] = wb[i];
    __syncthreads();

    const int warp = threadIdx.x >> 5, lane = threadIdx.x & 31;
    const int n = blockIdx.x * 8 + warp;
    if (n >= Nn) return;
    const int ch = lane * 4;

    const float4 q = *(const float4*)&g_qkvs[(size_t)n * 512 + ch];
    const int s = g_rowptr[n], e = g_rowptr[n + 1];

    float ax = 0.f, ay = 0.f, az = 0.f, aw = 0.f, den = 0.f;
    float bx = 0.f, by = 0.f, bz = 0.f, bw = 0.f, den2 = 0.f;

    int s1c = 0, s2c = 0;
    float ev1c = 0.f, ev2c = 0.f;
    if (s + 1 < e) {
        int e1 = g_eidx[s], e2 = g_eidx[s + 1];
        s1c = ei[e1]; s2c = ei[e2];
        ev1c = (lane < EDd) ? ea[(size_t)e1 * EDd + lane] : 0.f;
        ev2c = (lane < EDd) ? ea[(size_t)e2 * EDd + lane] : 0.f;
    }

    int j = s;
    for (; j + 1 < e; j += 2) {
        int s1n = 0, s2n = 0;
        float ev1n = 0.f, ev2n = 0.f;
        if (j + 3 < e) {
            int e1 = g_eidx[j + 2], e2 = g_eidx[j + 3];
            s1n = ei[e1]; s2n = ei[e2];
            ev1n = (lane < EDd) ? ea[(size_t)e1 * EDd + lane] : 0.f;
            ev2n = (lane < EDd) ? ea[(size_t)e2 * EDd + lane] : 0.f;
        }
        float4 k1 = *(const float4*)&g_qkvs[(size_t)s1c * 512 + 128 + ch];
        float4 k2 = *(const float4*)&g_qkvs[(size_t)s2c * 512 + 128 + ch];
        float4 v1 = *(const float4*)&g_qkvs[(size_t)s1c * 512 + 256 + ch];
        float4 v2 = *(const float4*)&g_qkvs[(size_t)s2c * 512 + 256 + ch];

        float p0 = sbe[ch], p1 = sbe[ch + 1], p2 = sbe[ch + 2], p3 = sbe[ch + 3];
        float r0 = p0, r1 = p1, r2 = p2, r3 = p3;
#pragma unroll
        for (int t = 0; t < EDd; t++) {
            float a1 = __shfl_sync(0xffffffffu, ev1c, t);
            float a2 = __shfl_sync(0xffffffffu, ev2c, t);
            float w0 = sWe[t * Dd + ch], w1 = sWe[t * Dd + ch + 1];
            float w2 = sWe[t * Dd + ch + 2], w3 = sWe[t * Dd + ch + 3];
            p0 += a1 * w0; p1 += a1 * w1; p2 += a1 * w2; p3 += a1 * w3;
            r0 += a2 * w0; r1 += a2 * w1; r2 += a2 * w2; r3 += a2 * w3;
        }
        float d1 = q.x * (k1.x + p0) + q.y * (k1.y + p1) + q.z * (k1.z + p2) + q.w * (k1.w + p3);
        float d2 = q.x * (k2.x + r0) + q.y * (k2.y + r1) + q.z * (k2.z + r2) + q.w * (k2.w + r3);
        d1 += __shfl_xor_sync(0xffffffffu, d1, 1);
        d2 += __shfl_xor_sync(0xffffffffu, d2, 1);
        d1 += __shfl_xor_sync(0xffffffffu, d1, 2);
        d2 += __shfl_xor_sync(0xffffffffu, d2, 2);
        float x1 = __expf(d1 * 0.25f);
        float x2 = __expf(d2 * 0.25f);
        den += x1; den2 += x2;
        ax += (v1.x + p0) * x1; ay += (v1.y + p1) * x1;
        az += (v1.z + p2) * x1; aw += (v1.w + p3) * x1;
        bx += (v2.x + r0) * x2; by += (v2.y + r1) * x2;
        bz += (v2.z + r2) * x2; bw += (v2.w + r3) * x2;

        s1c = s1n; s2c = s2n; ev1c = ev1n; ev2c = ev2n;
    }
    if (j < e) {
        const int e1 = g_eidx[j];
        const int s1 = ei[e1];
        float ev1 = (lane < EDd) ? ea[(size_t)e1 * EDd + lane] : 0.f;
        float4 k1 = *(const float4*)&g_qkvs[(size_t)s1 * 512 + 128 + ch];
        float4 v1 = *(const float4*)&g_qkvs[(size_t)s1 * 512 + 256 + ch];
        float p0 = sbe[ch], p1 = sbe[ch + 1], p2 = sbe[ch + 2], p3 = sbe[ch + 3];
#pragma unroll
        for (int t = 0; t < EDd; t++) {
            float a1 = __shfl_sync(0xffffffffu, ev1, t);
            p0 += a1 * sWe[t * Dd + ch];
            p1 += a1 * sWe[t * Dd + ch + 1];
            p2 += a1 * sWe[t * Dd + ch + 2];
            p3 += a1 * sWe[t * Dd + ch + 3];
        }
        float d1 = q.x * (k1.x + p0) + q.y * (k1.y + p1) + q.z * (k1.z + p2) + q.w * (k1.w + p3);
        d1 += __shfl_xor_sync(0xffffffffu, d1, 1);
        d1 += __shfl_xor_sync(0xffffffffu, d1, 2);
        float x1 = __expf(d1 * 0.25f);
        den += x1;
        ax += (v1.x + p0) * x1; ay += (v1.y + p1) * x1;
        az += (v1.z + p2) * x1; aw += (v1.w + p3) * x1;
    }
    ax += bx; ay += by; az += bz; aw += bw; den += den2;

    float inv = 1.f / (den + 1e-16f);
    ax *= inv; ay *= inv; az *= inv; aw *= inv;

    float4 xr = *(const float4*)&g_qkvs[(size_t)n * 512 + 384 + ch];
    float sdot =
        ax * swb[ch] + ay * swb[ch + 1] + az * swb[ch + 2] + aw * swb[ch + 3] +
        xr.x * swb[128 + ch] + xr.y * swb[128 + ch + 1] + xr.z * swb[128 + ch + 2] + xr.w * swb[128 + ch + 3] +
        (ax - xr.x) * swb[256 + ch] + (ay - xr.y) * swb[256 + ch + 1] +
        (az - xr.z) * swb[256 + ch + 2] + (aw - xr.w) * swb[256 + ch + 3];
#pragma unroll
    for (int o = 16; o; o >>= 1) sdot += __shfl_xor_sync(0xffffffffu, sdot, o);
    float beta = 1.f / (1.f + expf(-sdot));
    float4 hp = *(const float4*)&g_h[(size_t)n * Dd + ch];
    float t0 = beta * xr.x + (1.f - beta) * ax + hp.x;
    float t1 = beta * xr.y + (1.f - beta) * ay + hp.y;
    float t2 = beta * xr.z + (1.f - beta) * az + hp.z;
    float t3 = beta * xr.w + (1.f - beta) * aw + hp.w;
    float sm = t0 + t1 + t2 + t3;
    float sq = t0 * t0 + t1 * t1 + t2 * t2 + t3 * t3;
#pragma unroll
    for (int o = 16; o; o >>= 1) {
        sm += __shfl_xor_sync(0xffffffffu, sm, o);
        sq += __shfl_xor_sync(0xffffffffu, sq, o);
    }
    float mu = sm * (1.f / 128.f);
    float var = sq * (1.f / 128.f) - mu * mu;
    float rs = rsqrtf(var + 1e-5f);
    float4 o4;
    o4.x = (t0 - mu) * rs * sg1[ch]     + sb1[ch];
    o4.y = (t1 - mu) * rs * sg1[ch + 1] + sb1[ch + 1];
    o4.z = (t2 - mu) * rs * sg1[ch + 2] + sb1[ch + 2];
    o4.w = (t3 - mu) * rs * sg1[ch + 3] + sb1[ch + 3];
    *(float4*)&g_h[(size_t)n * Dd + ch] = o4;
    uint32_t h0, l0, h1, l1;
    split2(o4.x, o4.y, h0, l0);
    split2(o4.z, o4.w, h1, l1);
    *(uint2*)&g_Ath[(size_t)n * Dd + ch] = make_uint2(h0, h1);
    *(uint2*)&g_Atl[(size_t)n * Dd + ch] = make_uint2(l0, l1);
}

// ---------------- pooling ----------------
__global__ void __launch_bounds__(256) pool_k(const int* __restrict__ batch) {
    int warp = threadIdx.x >> 5, lane = threadIdx.x & 31;
    int n = blockIdx.x * 8 + warp;
    if (n >= Nn) return;
    int b = batch[n];
    int ch = lane * 4;
    float4 h4 = *(const float4*)&g_h[(size_t)n * Dd + ch];
    float* dp = &g_pool[(size_t)b * Dd + ch];
    asm volatile("red.global.add.v4.f32 [%0], {%1,%2,%3,%4};"
                 :: "l"(dp), "f"(h4.x), "f"(h4.y), "f"(h4.z), "f"(h4.w) : "memory");
    if (lane == 0) atomicAdd(&g_cnt[b], 1.f);
}
// divide by count and split straight into Ath/Atl (final GEMM reads those)
__global__ void __launch_bounds__(256) pool_fin_k() {
    int warp = threadIdx.x >> 5, lane = threadIdx.x & 31;
    int b = blockIdx.x * 8 + warp;
    if (b >= Bb) return;
    float c = fmaxf(g_cnt[b], 1.f);
    float inv = 1.f / c;
    int ch = lane * 4;
    float4 p = *(const float4*)&g_pool[(size_t)b * Dd + ch];
    p.x *= inv; p.y *= inv; p.z *= inv; p.w *= inv;
    uint32_t h0, l0, h1, l1;
    split2(p.x, p.y, h0, l0);
    split2(p.z, p.w, h1, l1);
    *(uint2*)&g_Ath[(size_t)b * Dd + ch] = make_uint2(h0, h1);
    *(uint2*)&g_Atl[(size_t)b * Dd + ch] = make_uint2(l0, l1);
}

// ---------------- host ----------------
extern "C" void kernel_launch(void* const* d_in, const int* in_sizes, int n_in,
                              void* d_out, int out_size)
{
    (void)in_sizes; (void)n_in; (void)out_size;
    const float* x     = (const float*)d_in[0];
    const float* ea    = (const float*)d_in[1];
    const int*   ei    = (const int*)  d_in[2];
    const int*   batch = (const int*)  d_in[3];
    const float* Wemb  = (const float*)d_in[4];
    const float* bemb  = (const float*)d_in[5];
    const float* Wout  = (const float*)d_in[6];
    const float* bout  = (const float*)d_in[7];
    const float* Wq = (const float*)d_in[8];  const float* bq = (const float*)d_in[9];
    const float* Wk = (const float*)d_in[10]; const float* bk = (const float*)d_in[11];
    const float* Wv = (const float*)d_in[12]; const float* bv = (const float*)d_in[13];
    const float* We = (const float*)d_in[14]; const float* be = (const float*)d_in[15];
    const float* Ws = (const float*)d_in[16]; const float* bs = (const float*)d_in[17];
    const float* Wbeta = (const float*)d_in[18];
    const float* g1 = (const float*)d_in[19]; const float* b1 = (const float*)d_in[20];
    const float* g2 = (const float*)d_in[21]; const float* b2 = (const float*)d_in[22];
    const float* Wf1 = (const float*)d_in[23]; const float* bf1 = (const float*)d_in[24];
    const float* Wf2 = (const float*)d_in[25]; const float* bf2 = (const float*)d_in[26];
    float* out = (float*)d_out;

    float *p_h, *p_qkvs, *p_packb;
    ushort_t *p_Wh, *p_Wl, *p_Ath, *p_Atl, *p_Fth, *p_Ftl;
    cudaGetSymbolAddress((void**)&p_h,     g_h);
    cudaGetSymbolAddress((void**)&p_qkvs,  g_qkvs);
    cudaGetSymbolAddress((void**)&p_packb, g_packb);
    cudaGetSymbolAddress((void**)&p_Wh,    g_Wh);
    cudaGetSymbolAddress((void**)&p_Wl,    g_Wl);
    cudaGetSymbolAddress((void**)&p_Ath,   g_Ath);
    cudaGetSymbolAddress((void**)&p_Atl,   g_Atl);
    cudaGetSymbolAddress((void**)&p_Fth,   g_Fth);
    cudaGetSymbolAddress((void**)&p_Ftl,   g_Ftl);

    cudaFuncSetAttribute(gemm2_k<0>, cudaFuncAttributeMaxDynamicSharedMemorySize, SMEM_G2);
    cudaFuncSetAttribute(gemm2_k<1>, cudaFuncAttributeMaxDynamicSharedMemorySize, SMEM_G2);
    cudaFuncSetAttribute(gemm2_k<2>, cudaFuncAttributeMaxDynamicSharedMemorySize, SMEM_G2);
    cudaFuncSetAttribute(gemm2_k<3>, cudaFuncAttributeMaxDynamicSharedMemorySize, SMEM_G2);

    dim3 blk(256);
    const int mt = (Nn + 127) / 128;
    const int ng = (Nn + 7) / 8;

    split_a_k<<<(Nn * Dd + 255) / 256, blk>>>(x, FA, Nn);
    prep_all_k<<<(W_TOTAL + 255) / 256, blk>>>(Wemb, Wq, Wk, Wv, Ws, Wf1, Wf2, Wout,
                                               bq, bk, bv, bs);
    gemm2_k<2><<<dim3(mt, 1), blk, SMEM_G2>>>(p_Ath, p_Atl, Dd, Nn, 8,
                                              p_Wh + OFF_EMB, p_Wl + OFF_EMB, Dd,
                                              bemb, p_h, nullptr, nullptr, Dd, 0, nullptr, nullptr);
    gemm2_k<0><<<dim3(mt, 4), blk, SMEM_G2>>>(p_Ath, p_Atl, Dd, Nn, 8,
                                              p_Wh + OFF_QKV, p_Wl + OFF_QKV, Dd,
                                              p_packb, p_qkvs, nullptr, nullptr, 4 * Dd, 0, nullptr, nullptr);
    csr_hist_k<<<1024, blk>>>(ei);
    csr_scan_k<<<1, 1024>>>();
    csr_scatter_k<<<1024, blk>>>(ei);

    for (int l = 0; l < Ll; l++) {
        if (l > 0)
            gemm2_k<0><<<dim3(mt, 4), blk, SMEM_G2>>>(p_Ath, p_Atl, Dd, Nn, 8,
                                                      p_Wh + OFF_QKV + l * SZ_QKV, p_Wl + OFF_QKV + l * SZ_QKV, Dd,
                                                      p_packb + l * 4 * Dd, p_qkvs, nullptr, nullptr, 4 * Dd, 0,
                                                      nullptr, nullptr);

        edge_gather_k<<<ng, blk>>>(ei, ea, We + (size_t)l * EDd * Dd, be + l * Dd,
                                   Wbeta + l * 3 * Dd, g1 + l * Dd, b1 + l * Dd);

        gemm2_k<1><<<dim3(mt, 4), blk, SMEM_G2>>>(p_Ath, p_Atl, Dd, Nn, 8,
                                                  p_Wh + OFF_FF1 + l * SZ_QKV, p_Wl + OFF_FF1 + l * SZ_QKV, Dd,
                                                  bf1 + l * DFFd, nullptr, p_Fth, p_Ftl, DFFd, 1, nullptr, nullptr);

        gemm2_k<3><<<dim3(mt, 1), blk, SMEM_G2>>>(p_Fth, p_Ftl, DFFd, Nn, 32,
                                                  p_Wh + OFF_FF2 + l * SZ_QKV, p_Wl + OFF_FF2 + l * SZ_QKV, DFFd,
                                                  bf2 + l * Dd, nullptr, nullptr, nullptr, Dd, 0,
                                                  g2 + l * Dd, b2 + l * Dd);
    }

    pool_k<<<ng, blk>>>(batch);
    pool_fin_k<<<(Bb + 7) / 8, blk>>>();
    gemm2_k<0><<<dim3(4, 1), blk, SMEM_G2>>>(p_Ath, p_Atl, Dd, Bb, 8,
                                             p_Wh + OFF_OUT, p_Wl + OFF_OUT, Dd,
                                             bout, out, nullptr, nullptr, Dd, 0, nullptr, nullptr);
}